// round 2
// baseline (speedup 1.0000x reference)
#include <cuda_runtime.h>
#include <cuda_bf16.h>
#include <math.h>

#define NN 50000
#define EE 800000
#define FIN 128
#define FOUT 128   // HEADS*C_OUT
#define HEADS 4
#define COUT 32
#define NEG_SLOPE 0.2f

// ---------------- scratch (device globals; no allocation) ----------------
__device__ __align__(16) float g_h[NN * FOUT];      // projected features
__device__ __align__(16) float g_asrc[NN * HEADS];  // per-node src logits
__device__ __align__(16) float g_adst[NN * HEADS];  // per-node dst logits
__device__ int g_deg[NN];
__device__ int g_off[NN];
__device__ int g_cur[NN];
__device__ int g_csr_src[EE];

// ---------------- GEMM: h = x @ W  (fp32, 64x128 tile, K-chunk 8) --------
__global__ void gemm_kernel(const float* __restrict__ x, const float* __restrict__ W) {
    __shared__ __align__(16) float xs[8][64];
    __shared__ __align__(16) float ws[8][128];

    const int rowBase = blockIdx.x * 64;
    const int tid  = threadIdx.x;           // 256 threads
    const int tcol = tid & 15;              // 16 col groups
    const int trow = tid >> 4;              // 16 row groups

    float acc[4][8];
#pragma unroll
    for (int r = 0; r < 4; r++)
#pragma unroll
        for (int c = 0; c < 8; c++) acc[r][c] = 0.f;

    for (int kc = 0; kc < FIN; kc += 8) {
        // stage x tile (transposed) : 64 rows x 8 k
#pragma unroll
        for (int i = 0; i < 2; i++) {
            int idx = tid + i * 256;
            int r = idx >> 3, k = idx & 7;
            int gr = rowBase + r;
            xs[k][r] = (gr < NN) ? x[gr * FIN + kc + k] : 0.f;
        }
        // stage W tile: 8 k x 128 cols
#pragma unroll
        for (int i = 0; i < 4; i++) {
            int idx = tid + i * 256;
            int k = idx >> 7, c = idx & 127;
            ws[k][c] = W[(kc + k) * FOUT + c];
        }
        __syncthreads();

#pragma unroll
        for (int k = 0; k < 8; k++) {
            float4 xv = *(const float4*)&xs[k][trow * 4];
            float4 wa = *(const float4*)&ws[k][tcol * 4];
            float4 wb = *(const float4*)&ws[k][64 + tcol * 4];
            float xr[4] = {xv.x, xv.y, xv.z, xv.w};
#pragma unroll
            for (int r = 0; r < 4; r++) {
                acc[r][0] += xr[r] * wa.x;
                acc[r][1] += xr[r] * wa.y;
                acc[r][2] += xr[r] * wa.z;
                acc[r][3] += xr[r] * wa.w;
                acc[r][4] += xr[r] * wb.x;
                acc[r][5] += xr[r] * wb.y;
                acc[r][6] += xr[r] * wb.z;
                acc[r][7] += xr[r] * wb.w;
            }
        }
        __syncthreads();
    }

#pragma unroll
    for (int r = 0; r < 4; r++) {
        int gr = rowBase + trow * 4 + r;
        if (gr < NN) {
            float4 va = make_float4(acc[r][0], acc[r][1], acc[r][2], acc[r][3]);
            float4 vb = make_float4(acc[r][4], acc[r][5], acc[r][6], acc[r][7]);
            *(float4*)&g_h[gr * FOUT + tcol * 4] = va;
            *(float4*)&g_h[gr * FOUT + 64 + tcol * 4] = vb;
        }
    }
}

// ---------------- per-node attention logits (warp per node) --------------
__global__ void a_kernel(const float* __restrict__ att_src, const float* __restrict__ att_dst) {
    int warp = (blockIdx.x * blockDim.x + threadIdx.x) >> 5;
    int lane = threadIdx.x & 31;
    if (warp >= NN) return;

    float4 hv = *(const float4*)&g_h[warp * FOUT + lane * 4];
    int head = lane >> 3;
    int off  = (lane & 7) * 4;
    const float* as = att_src + head * COUT + off;
    const float* ad = att_dst + head * COUT + off;
    float ps = hv.x * as[0] + hv.y * as[1] + hv.z * as[2] + hv.w * as[3];
    float pd = hv.x * ad[0] + hv.y * ad[1] + hv.z * ad[2] + hv.w * ad[3];
#pragma unroll
    for (int d = 4; d >= 1; d >>= 1) {
        ps += __shfl_xor_sync(0xffffffffu, ps, d);
        pd += __shfl_xor_sync(0xffffffffu, pd, d);
    }
    if ((lane & 7) == 0) {
        g_asrc[warp * HEADS + head] = ps;
        g_adst[warp * HEADS + head] = pd;
    }
}

// ---------------- CSR build ----------------------------------------------
__global__ void zero_deg_kernel() {
    int i = blockIdx.x * blockDim.x + threadIdx.x;
    if (i < NN) g_deg[i] = 0;
}

// edges are INT32 (JAX x64 is disabled; jnp "int64" arrays are int32).
// layout: edges[0:EE] = src, edges[EE:2EE] = dst
__global__ void hist_kernel(const int* __restrict__ edges) {
    int e = blockIdx.x * blockDim.x + threadIdx.x;
    if (e < EE) {
        int dst = edges[EE + e];
        atomicAdd(&g_deg[dst], 1);
    }
}

__global__ void scan_kernel() {   // 1 block, 1024 threads, exclusive scan of g_deg
    __shared__ int ssum[1024];
    const int CH = (NN + 1023) / 1024;   // 49
    int t = threadIdx.x;
    int base = t * CH;

    int s = 0;
    for (int i = 0; i < CH; i++) {
        int idx = base + i;
        if (idx < NN) s += g_deg[idx];
    }
    ssum[t] = s;
    __syncthreads();
    for (int d = 1; d < 1024; d <<= 1) {
        int v = 0;
        if (t >= d) v = ssum[t - d];
        __syncthreads();
        ssum[t] += v;
        __syncthreads();
    }
    int prefix = (t > 0) ? ssum[t - 1] : 0;
    for (int i = 0; i < CH; i++) {
        int idx = base + i;
        if (idx < NN) {
            g_off[idx] = prefix;
            g_cur[idx] = prefix;
            prefix += g_deg[idx];
        }
    }
}

__global__ void scatter_kernel(const int* __restrict__ edges) {
    int e = blockIdx.x * blockDim.x + threadIdx.x;
    if (e < EE) {
        int src = edges[e];
        int dst = edges[EE + e];
        int pos = atomicAdd(&g_cur[dst], 1);
        g_csr_src[pos] = src;
    }
}

// ---------------- GAT aggregate: warp per dst node -----------------------
__global__ void gat_kernel(const float* __restrict__ bias, float* __restrict__ out) {
    int warp = (blockIdx.x * blockDim.x + threadIdx.x) >> 5;
    int lane = threadIdx.x & 31;
    if (warp >= NN) return;
    const int n = warp;

    const int start = g_off[n];
    const int deg   = g_deg[n];
    const int lane4 = lane * 4;
    float4 bv = *(const float4*)&bias[lane4];

    if (deg == 0) {
        *(float4*)&out[n * FOUT + lane4] = bv;
        return;
    }

    float4 ad4 = *(const float4*)&g_adst[n * HEADS];
    float adh[4] = {ad4.x, ad4.y, ad4.z, ad4.w};

    // ---- pass 1: online softmax stats per head, lane-parallel over edges
    float m[4] = {-1e30f, -1e30f, -1e30f, -1e30f};
    float s[4] = {0.f, 0.f, 0.f, 0.f};
    for (int i = lane; i < deg; i += 32) {
        int src = g_csr_src[start + i];
        float4 as4 = *(const float4*)&g_asrc[src * HEADS];
        float ev[4] = {as4.x + adh[0], as4.y + adh[1], as4.z + adh[2], as4.w + adh[3]};
#pragma unroll
        for (int h = 0; h < 4; h++) {
            float e = ev[h];
            e = (e > 0.f) ? e : NEG_SLOPE * e;
            float nm = fmaxf(m[h], e);
            s[h] = s[h] * __expf(m[h] - nm) + __expf(e - nm);
            m[h] = nm;
        }
    }
    // warp combine (safe with -1e30 sentinel: no inf-inf NaN)
#pragma unroll
    for (int h = 0; h < 4; h++) {
#pragma unroll
        for (int d = 16; d >= 1; d >>= 1) {
            float mo = __shfl_xor_sync(0xffffffffu, m[h], d);
            float so = __shfl_xor_sync(0xffffffffu, s[h], d);
            float nm = fmaxf(m[h], mo);
            s[h] = s[h] * __expf(m[h] - nm) + so * __expf(mo - nm);
            m[h] = nm;
        }
    }

    const int hl = lane >> 3;
    float mh  = (hl == 0) ? m[0] : (hl == 1) ? m[1] : (hl == 2) ? m[2] : m[3];
    float sh  = (hl == 0) ? s[0] : (hl == 1) ? s[1] : (hl == 2) ? s[2] : s[3];
    float inv = 1.f / fmaxf(sh, 1e-16f);
    float adl = (hl == 0) ? adh[0] : (hl == 1) ? adh[1] : (hl == 2) ? adh[2] : adh[3];

    // ---- pass 2: weighted aggregate; lane owns 4 contiguous channels
    float4 acc = make_float4(0.f, 0.f, 0.f, 0.f);
#pragma unroll 4
    for (int i = 0; i < deg; i++) {
        int src = g_csr_src[start + i];                 // broadcast load
        float asv = g_asrc[src * HEADS + hl];           // 1-sector broadcast
        float e = asv + adl;
        e = (e > 0.f) ? e : NEG_SLOPE * e;
        float alpha = __expf(e - mh) * inv;
        float4 hv = *(const float4*)&g_h[src * FOUT + lane4];  // 512B/warp, L2
        acc.x += alpha * hv.x;
        acc.y += alpha * hv.y;
        acc.z += alpha * hv.z;
        acc.w += alpha * hv.w;
    }
    acc.x += bv.x; acc.y += bv.y; acc.z += bv.z; acc.w += bv.w;
    *(float4*)&out[n * FOUT + lane4] = acc;
}

// ---------------- launch --------------------------------------------------
extern "C" void kernel_launch(void* const* d_in, const int* in_sizes, int n_in,
                              void* d_out, int out_size) {
    const float* x       = (const float*)d_in[0];
    const int*   edges   = (const int*)d_in[1];    // int32! (JAX x64 disabled)
    const float* W       = (const float*)d_in[2];
    const float* att_src = (const float*)d_in[3];
    const float* att_dst = (const float*)d_in[4];
    const float* bias    = (const float*)d_in[5];
    float*       out     = (float*)d_out;

    gemm_kernel<<<(NN + 63) / 64, 256>>>(x, W);
    a_kernel<<<(NN * 32 + 255) / 256, 256>>>(att_src, att_dst);
    zero_deg_kernel<<<(NN + 255) / 256, 256>>>();
    hist_kernel<<<(EE + 255) / 256, 256>>>(edges);
    scan_kernel<<<1, 1024>>>();
    scatter_kernel<<<(EE + 255) / 256, 256>>>(edges);
    gat_kernel<<<(NN * 32 + 255) / 256, 256>>>(bias, out);
}